// round 3
// baseline (speedup 1.0000x reference)
#include <cuda_runtime.h>
#include <cstdint>

#define N_NODES 50000
#define IN_FEAT 512
#define OUT_FEAT 256
#define N_EDGES 1600000
#define ALPHA 0.2f

// Scratch (allocation-free rule: __device__ globals).
// Declared as float4 so 128-bit loads are legally aligned.
__device__ float4 g_w_src4[IN_FEAT / 4];
__device__ float4 g_w_tgt4[IN_FEAT / 4];
__device__ float g_s_src[N_NODES];
__device__ float g_s_tgt[N_NODES];

// ---------------------------------------------------------------------------
// Kernel A: w_src = W @ a_src, w_tgt = W @ a_tgt.  One warp per row of W.
// W is [IN_FEAT, OUT_FEAT] row-major. attn_w is [2*OUT_FEAT].
// ---------------------------------------------------------------------------
__global__ void compute_w_kernel(const float* __restrict__ W,
                                 const float* __restrict__ attn_w) {
    int warp = (blockIdx.x * blockDim.x + threadIdx.x) >> 5;
    int lane = threadIdx.x & 31;
    if (warp >= IN_FEAT) return;

    const float* wrow = W + (size_t)warp * OUT_FEAT;
    float acc_s = 0.f, acc_t = 0.f;
#pragma unroll
    for (int c = 0; c < OUT_FEAT; c += 32) {
        float wv = wrow[c + lane];
        acc_s += wv * attn_w[c + lane];
        acc_t += wv * attn_w[OUT_FEAT + c + lane];
    }
#pragma unroll
    for (int off = 16; off > 0; off >>= 1) {
        acc_s += __shfl_xor_sync(0xffffffffu, acc_s, off);
        acc_t += __shfl_xor_sync(0xffffffffu, acc_t, off);
    }
    if (lane == 0) {
        // scalar store into the float4 arrays
        reinterpret_cast<float*>(g_w_src4)[warp] = acc_s;
        reinterpret_cast<float*>(g_w_tgt4)[warp] = acc_t;
    }
}

// ---------------------------------------------------------------------------
// Kernel B: per-node scores. One warp per node, float4 coalesced loads.
// s_src[i] = h[i,:] . w_src ; s_tgt[i] = h[i,:] . w_tgt
// ---------------------------------------------------------------------------
__global__ void node_scores_kernel(const float* __restrict__ h) {
    __shared__ float4 sh_ws[IN_FEAT / 4];
    __shared__ float4 sh_wt[IN_FEAT / 4];

    for (int i = threadIdx.x; i < IN_FEAT / 4; i += blockDim.x) {
        sh_ws[i] = g_w_src4[i];
        sh_wt[i] = g_w_tgt4[i];
    }
    __syncthreads();

    int warp_in_block = threadIdx.x >> 5;
    int lane = threadIdx.x & 31;
    int node = blockIdx.x * (blockDim.x >> 5) + warp_in_block;
    if (node >= N_NODES) return;

    const float4* h4 = reinterpret_cast<const float4*>(h + (size_t)node * IN_FEAT);

    float acc_s = 0.f, acc_t = 0.f;
#pragma unroll
    for (int i = 0; i < 4; i++) {              // 4 iters * 32 lanes * 4 floats = 512
        int idx = i * 32 + lane;
        float4 hv = h4[idx];
        float4 ws = sh_ws[idx];
        float4 wt = sh_wt[idx];
        acc_s += hv.x * ws.x + hv.y * ws.y + hv.z * ws.z + hv.w * ws.w;
        acc_t += hv.x * wt.x + hv.y * wt.y + hv.z * wt.z + hv.w * wt.w;
    }
#pragma unroll
    for (int off = 16; off > 0; off >>= 1) {
        acc_s += __shfl_xor_sync(0xffffffffu, acc_s, off);
        acc_t += __shfl_xor_sync(0xffffffffu, acc_t, off);
    }
    if (lane == 0) {
        g_s_src[node] = acc_s;
        g_s_tgt[node] = acc_t;
    }
}

// ---------------------------------------------------------------------------
// Kernel C: per-edge gather + leaky_relu.
// edge_list is [2, N_EDGES] int32 (JAX silently downcasts int64 -> int32):
// row 0 = source, row 1 = target.
// ---------------------------------------------------------------------------
__global__ void edge_kernel(const int* __restrict__ edge_list,
                            float* __restrict__ out) {
    int k = blockIdx.x * blockDim.x + threadIdx.x;
    if (k >= N_EDGES) return;
    int s = edge_list[k];
    int t = edge_list[N_EDGES + k];
    float e = __ldg(&g_s_src[s]) + __ldg(&g_s_tgt[t]);
    out[k] = (e > 0.f) ? e : ALPHA * e;
}

// ---------------------------------------------------------------------------
extern "C" void kernel_launch(void* const* d_in, const int* in_sizes, int n_in,
                              void* d_out, int out_size) {
    const float* h         = (const float*)d_in[0];
    const int*   edge_list = (const int*)d_in[1];
    const float* W         = (const float*)d_in[2];
    const float* attn_w    = (const float*)d_in[3];
    float* out = (float*)d_out;

    // A: 512 warps -> 64 blocks x 256 threads
    compute_w_kernel<<<64, 256>>>(W, attn_w);

    // B: warp per node, 8 warps/block
    node_scores_kernel<<<(N_NODES + 7) / 8, 256>>>(h);

    // C: thread per edge
    edge_kernel<<<(N_EDGES + 255) / 256, 256>>>(edge_list, out);
}